// round 1
// baseline (speedup 1.0000x reference)
#include <cuda_runtime.h>
#include <stdint.h>

// FP32 bit-pulse -> FP8 E4M3 bit-pulse converter.
// Input : N*32 floats, each 0.0f or 1.0f, row layout [S, E7..E0, M22..M0] MSB first
// Output: N*8  floats, row layout [S, E3..E0, M2..M0]
//
// Strategy: one thread per row. Reinterpret the 32 floats as uints; a pulse of
// 1.0f is 0x3F800000 (bit 29 set), 0.0f is all-zero, so (u >> 29) & 1 extracts
// the bit. Pack the 32 pulses into one uint32 shaped exactly like an IEEE754
// float word, then do the E4M3 RNE conversion with plain integer ALU.

__global__ __launch_bounds__(256) void fp32_to_fp8_pulse_kernel(
    const uint4* __restrict__ in,   // 8 x uint4 per row (32 words)
    float4* __restrict__ out,       // 2 x float4 per row (8 floats)
    int nrows)
{
    int row = blockIdx.x * blockDim.x + threadIdx.x;
    if (row >= nrows) return;

    const uint4* p = in + (size_t)row * 8;

    // Load all 8 uint4 first (8 independent LDG.128 -> MLP=8), then pack.
    uint4 v[8];
#pragma unroll
    for (int k = 0; k < 8; k++) v[k] = p[k];

    // packed: bit 31 = element 0 (sign), ..., bit 0 = element 31 (M0)
    uint32_t packed = 0;
#pragma unroll
    for (int k = 0; k < 8; k++) {
        uint32_t nib = ((v[k].x >> 29) & 1u) << 3
                     | ((v[k].y >> 29) & 1u) << 2
                     | ((v[k].z >> 29) & 1u) << 1
                     | ((v[k].w >> 29) & 1u);
        packed = (packed << 4) | nib;
    }

    uint32_t s    = packed >> 31;
    uint32_t exp  = (packed >> 23) & 0xFFu;
    uint32_t mant = packed & 0x7FFFFFu;

    // ---- normal path: fp8_exp = exp - 120, RNE round 23 -> 3 mantissa bits ----
    uint32_t kept = mant >> 20;
    uint32_t R    = (mant >> 19) & 1u;
    uint32_t S    = (mant & ((1u << 19) - 1u)) != 0u;
    uint32_t L    = kept & 1u;
    uint32_t mr   = kept + (R & (S | L));
    uint32_t carry = mr >> 3;
    uint32_t mant_norm = carry ? 0u : (mr & 7u);
    uint32_t exp_norm  = exp - 120u + carry;   // only consumed when exp in (120,134]

    // ---- subnormal path (117 <= exp <= 120): shift 1.mant right, RNE ----
    uint32_t full = (1u << 23) | mant;
    int shi = 141 - (int)exp;
    if (shi < 1)  shi = 1;
    if (shi > 24) shi = 24;
    uint32_t sh = (uint32_t)shi;
    uint32_t kept_s = full >> sh;
    uint32_t Rs = (full >> (sh - 1u)) & 1u;
    uint32_t Ss = (full & ((1u << (sh - 1u)) - 1u)) != 0u;
    uint32_t Ls = kept_s & 1u;
    uint32_t ms = kept_s + (Rs & (Ss | Ls));
    uint32_t sub_exp  = (ms >= 8u) ? 1u : 0u;
    uint32_t sub_mant = (ms >= 8u) ? 0u : ms;

    // ---- select overflow / subnormal / underflow / normal ----
    uint32_t exp8, mant8;
    if (exp > 134u)                      { exp8 = 15u;      mant8 = 6u;        }
    else if (exp >= 117u && exp <= 120u) { exp8 = sub_exp;  mant8 = sub_mant;  }
    else if (exp < 117u)                 { exp8 = 0u;       mant8 = 0u;        }
    else                                 { exp8 = exp_norm; mant8 = mant_norm; }

    float4 o0, o1;
    o0.x = (float)s;
    o0.y = (float)((exp8 >> 3) & 1u);
    o0.z = (float)((exp8 >> 2) & 1u);
    o0.w = (float)((exp8 >> 1) & 1u);
    o1.x = (float)(exp8 & 1u);
    o1.y = (float)((mant8 >> 2) & 1u);
    o1.z = (float)((mant8 >> 1) & 1u);
    o1.w = (float)(mant8 & 1u);

    out[(size_t)row * 2]     = o0;
    out[(size_t)row * 2 + 1] = o1;
}

extern "C" void kernel_launch(void* const* d_in, const int* in_sizes, int n_in,
                              void* d_out, int out_size)
{
    const uint4* in = (const uint4*)d_in[0];
    float4* out = (float4*)d_out;
    int nrows = in_sizes[0] / 32;

    int threads = 256;
    int blocks = (nrows + threads - 1) / threads;
    fp32_to_fp8_pulse_kernel<<<blocks, threads>>>(in, out, nrows);
}